// round 12
// baseline (speedup 1.0000x reference)
#include <cuda_runtime.h>
#include <cstdint>

#define B_     8
#define N_     2048
#define FIN    256
#define FOUT   64
#define LOG2E  1.4426950408889634f
#define ONE_TF 0x3f800000u

// Scratch (device globals: allocation-free rule)
__device__ float    g_WhB[B_ * N_ * FOUT];  // [b][j>>3][o][j&7], tf32-pre-rounded
__device__ float    g_esrc[B_ * N_];        // log2-scaled src logits
__device__ float2   g_edEF[B_ * N_];        // per node: (exp2(d), exp2(0.2 d))

// ---------------------------------------------------------------------------
// helpers
// ---------------------------------------------------------------------------
__device__ __forceinline__ uint32_t smem_u32(const void* p) {
    uint32_t a;
    asm("{ .reg .u64 t; cvta.to.shared.u64 t, %1; cvt.u32.u64 %0, t; }" : "=r"(a) : "l"(p));
    return a;
}
__device__ __forceinline__ void cpa16(uint32_t dst, const void* src) {
    asm volatile("cp.async.cg.shared.global [%0], [%1], 16;" :: "r"(dst), "l"(src));
}
#define CP_COMMIT() asm volatile("cp.async.commit_group;" ::: "memory")
#define CP_WAIT1()  asm volatile("cp.async.wait_group 1;" ::: "memory")
#define BAR_PAIR(id) asm volatile("bar.sync %0, 128;" :: "r"(id) : "memory")

__device__ __forceinline__ float ex2f(float x) {
    float r; asm("ex2.approx.f32 %0, %1;" : "=f"(r) : "f"(x)); return r;
}
__device__ __forceinline__ uint32_t tf32u(float x) {
    uint32_t r; asm("cvt.rn.tf32.f32 %0, %1;" : "=r"(r) : "f"(x)); return r;
}
// D += A*B, m16n8k8 tf32 (base PTX ISA)
#define MMA_TF32(d, a0, a1, a2, a3, b0, b1)                                   \
    asm volatile("mma.sync.aligned.m16n8k8.row.col.f32.tf32.tf32.f32 "        \
                 "{%0,%1,%2,%3}, {%4,%5,%6,%7}, {%8,%9}, {%0,%1,%2,%3};"      \
                 : "+f"((d)[0]), "+f"((d)[1]), "+f"((d)[2]), "+f"((d)[3])     \
                 : "r"(a0), "r"(a1), "r"(a2), "r"(a3), "r"(b0), "r"(b1))

// packed fp32x2 FMA (prep kernel)
#define FMA2(d, a, b) asm("fma.rn.f32x2 %0, %1, %2, %0;" : "+l"(d) : "l"(a), "l"(b))
__device__ __forceinline__ float pair_sum(unsigned long long v) {
    float lo, hi;
    asm("mov.b64 {%0, %1}, %2;" : "=f"(lo), "=f"(hi) : "l"(v));
    return lo + hi;
}
__device__ __forceinline__ unsigned long long pack2(float lo, float hi) {
    unsigned long long r;
    asm("mov.b64 %0, {%1, %2};" : "=l"(r) : "f"(lo), "f"(hi));
    return r;
}

// ---------------------------------------------------------------------------
// Kernel PREP: Wh = h @ W via FFMA2. 256 blocks x 256 threads, 64 rows/block,
// 2 blocks/SM (84KB smem). ALL of W staged pair-packed ONCE (64KB) -- no
// per-quarter re-staging; h chunks (64 rows x 32k) double-buffered cp.async;
// one barrier pair per chunk. Stores g_WhB (tf32, fragment layout),
// g_esrc (log2-scaled), g_edEF = (exp2(d), exp2(0.2d)).
// ---------------------------------------------------------------------------
#define HB_OFF 65536      // byte offset of h buffers (2 x 9216)

__global__ __launch_bounds__(256, 2) void gat_prep(const float* __restrict__ h,
                                                   const float* __restrict__ W,
                                                   const float* __restrict__ a) {
    extern __shared__ char sA[];
    unsigned long long* Wp = (unsigned long long*)sA;   // 8192 ull = 64KB
    float* hb = (float*)(sA + HB_OFF);                  // 2 x (64 rows x 36)
    uint32_t hbase = smem_u32(sA) + HB_OFF;

    int t = threadIdx.x;
    int rg = t >> 4, op = t & 15;
    int row0 = blockIdx.x * 64;

    // h chunk issue: 64 rows x 32 k = 512 x 16B, 2 cp.async per thread
    int r0 = t >> 3, f0 = t & 7;
    int r1 = (t + 256) >> 3, f1 = t & 7;   // second half
    const float* hsrc = h + (size_t)row0 * FIN;

    {   // chunks 0, 1
        cpa16(hbase + r0 * 144 + f0 * 16, hsrc + (size_t)r0 * FIN + f0 * 4);
        cpa16(hbase + r1 * 144 + f1 * 16, hsrc + (size_t)r1 * FIN + f1 * 4);
        CP_COMMIT();
        cpa16(hbase + 9216 + r0 * 144 + f0 * 16, hsrc + (size_t)r0 * FIN + 32 + f0 * 4);
        cpa16(hbase + 9216 + r1 * 144 + f1 * 16, hsrc + (size_t)r1 * FIN + 32 + f1 * 4);
        CP_COMMIT();
    }

    // stage ALL W pairs: Wp[kp*64+o] = (W[2kp][o], W[2kp+1][o]), kp 0..127
#pragma unroll 4
    for (int idx = t; idx < 8192; idx += 256) {
        int kp = idx >> 6, o = idx & 63;
        Wp[idx] = pack2(__ldg(W + (2 * kp) * FOUT + o), __ldg(W + (2 * kp + 1) * FOUT + o));
    }

    unsigned long long acc[4][4];
#pragma unroll
    for (int q = 0; q < 4; q++)
#pragma unroll
        for (int s = 0; s < 4; s++) acc[q][s] = 0ull;

    for (int c = 0; c < 8; c++) {
        CP_WAIT1();
        __syncthreads();                    // h chunk ready; also covers Wp on c==0
        const float* hc = hb + (c & 1) * 2304;
#pragma unroll
        for (int kpl = 0; kpl < 16; kpl++) {
            const ulonglong2* wrow = (const ulonglong2*)(Wp + (c * 16 + kpl) * 64);
            ulonglong2 wa = wrow[op];
            ulonglong2 wb = wrow[op + 16];
#pragma unroll
            for (int q = 0; q < 4; q++) {
                unsigned long long hv =
                    *(const unsigned long long*)(hc + (rg * 4 + q) * 36 + 2 * kpl);
                FMA2(acc[q][0], hv, wa.x);
                FMA2(acc[q][1], hv, wa.y);
                FMA2(acc[q][2], hv, wb.x);
                FMA2(acc[q][3], hv, wb.y);
            }
        }
        __syncthreads();                    // done reading hb[c&1]
        if (c + 2 < 8) {
            uint32_t dst = hbase + (c & 1) * 9216;
            const float* src = hsrc + (c + 2) * 32;
            cpa16(dst + r0 * 144 + f0 * 16, src + (size_t)r0 * FIN + f0 * 4);
            cpa16(dst + r1 * 144 + f1 * 16, src + (size_t)r1 * FIN + f1 * 4);
        }
        CP_COMMIT();
    }

    int ov[4] = {2 * op, 2 * op + 1, 2 * op + 32, 2 * op + 33};
    float a1v[4], a2v[4];
#pragma unroll
    for (int s = 0; s < 4; s++) { a1v[s] = a[ov[s]]; a2v[s] = a[FOUT + ov[s]]; }

#pragma unroll
    for (int q = 0; q < 4; q++) {
        int grow = row0 + rg * 4 + q;
        int b = grow >> 11, n = grow & (N_ - 1);
        float vals[4], v1 = 0.f, v2 = 0.f;
#pragma unroll
        for (int s = 0; s < 4; s++) {
            vals[s] = pair_sum(acc[q][s]);
            v1 += vals[s] * a1v[s];
            v2 += vals[s] * a2v[s];
        }
        size_t base = ((size_t)b * 256 + (n >> 3)) * 512 + (n & 7);
#pragma unroll
        for (int s = 0; s < 4; s++)
            g_WhB[base + (size_t)ov[s] * 8] = __uint_as_float(tf32u(vals[s]));
#pragma unroll
        for (int off = 1; off < 16; off <<= 1) {
            v1 += __shfl_xor_sync(0xffffffffu, v1, off);
            v2 += __shfl_xor_sync(0xffffffffu, v2, off);
        }
        if (op == 0) {
            float s = v1 * LOG2E, d = v2 * LOG2E;
            g_esrc[grow] = s;
            g_edEF[grow] = make_float2(ex2f(d), ex2f(0.2f * d));
        }
    }
}

// ---------------------------------------------------------------------------
// Kernel B: streaming attention -> mma.sync tf32 P @ Wh.
// Grid (32,8)=256 blocks x 256 threads, 2 blocks/SM.
// 2 PAIRS of 4 warps: jq = w>>2 (j-half), wp = w&3 (one m16 fragment).
// Wh + EF staged via triple-buffered cp.async (8.4KB slices); adj read
// DIRECTLY to registers via __ldcs LDG.64, software-pipelined one chunk
// ahead (no smem round-trip -> L1 traffic cut). adj touched once chip-wide.
// p = adj>0 ? max(Ei*Ej, Fi*Fj) : 0 (== exp2(leaky)), tf32.
// Rowsum via ones-B MMA (same tf32 p -> exact normalization).
// ---------------------------------------------------------------------------
#define EF_OFF   8192
#define SLICE_SZ 8448                      // 8192 Wh + 256 EF
#define SM_TOTB  (2 * 3 * SLICE_SZ)        // 50688

__device__ __forceinline__ void pf_slice(uint32_t dst, const char* whsrc,
                                         const float2* efsrc, int jq, int cc, int lt) {
    const char* wsrc = whsrc + (size_t)(jq * 128 + cc * 4) * 2048;
#pragma unroll
    for (int i = 0; i < 4; i++)
        cpa16(dst + (lt + 128 * i) * 16, wsrc + (size_t)(lt + 128 * i) * 16);
    if (lt < 16)
        cpa16(dst + EF_OFF + lt * 16,
              (const char*)(efsrc + (size_t)jq * 1024 + cc * 32) + lt * 16);
}

__global__ __launch_bounds__(256, 2) void gat_attn(const int* __restrict__ adj,
                                                   float* __restrict__ out) {
    extern __shared__ char sm[];
    uint32_t smb = smem_u32(sm);

    int t = threadIdx.x;
    int w = t >> 5, lane = t & 31;
    int q = lane >> 2, c = lane & 3;
    int b = blockIdx.y;
    int i0 = blockIdx.x * 64;
    int rowbase = b * N_;
    int jq = w >> 2, wp = w & 3;
    int lr0 = wp * 16 + q;
    int lt = t & 127;
    uint32_t slice0 = smb + jq * 3 * SLICE_SZ;

    const char*   whsrc = (const char*)(g_WhB + (size_t)b * N_ * FOUT);
    const float2* efsrc = g_edEF + rowbase;

    float si0 = g_esrc[rowbase + i0 + lr0];
    float si8 = g_esrc[rowbase + i0 + lr0 + 8];
    float Ei0 = ex2f(si0), Fi0 = ex2f(0.2f * si0);
    float Ei8 = ex2f(si8), Fi8 = ex2f(0.2f * si8);

    // direct adj row pointers (this lane's two rows), j offset jq*1024 + 2c
    const int* adjr0 = adj + ((size_t)(rowbase + i0 + lr0) << 11) + jq * 1024 + 2 * c;
    const int* adjr8 = adjr0 + (8 << 11);

    // prologue: chunk 0 adj
    int2 A0[4], A8[4], nA0[4], nA8[4];
#pragma unroll
    for (int ks = 0; ks < 4; ks++) {
        A0[ks] = __ldcs((const int2*)(adjr0 + ks * 8));
        A8[ks] = __ldcs((const int2*)(adjr8 + ks * 8));
    }

    pf_slice(slice0, whsrc, efsrc, jq, 0, lt);            CP_COMMIT();
    pf_slice(slice0 + SLICE_SZ, whsrc, efsrc, jq, 1, lt); CP_COMMIT();

    float acc[8][4];
#pragma unroll
    for (int nt = 0; nt < 8; nt++)
#pragma unroll
        for (int s = 0; s < 4; s++) acc[nt][s] = 0.f;
    float acc_rs[4] = {0.f, 0.f, 0.f, 0.f};

#pragma unroll 1
    for (int cc = 0; cc < 32; cc++) {
        if (cc + 1 < 32) {
            const int* p0 = adjr0 + (cc + 1) * 32;
            const int* p8 = adjr8 + (cc + 1) * 32;
#pragma unroll
            for (int ks = 0; ks < 4; ks++) {
                nA0[ks] = __ldcs((const int2*)(p0 + ks * 8));
                nA8[ks] = __ldcs((const int2*)(p8 + ks * 8));
            }
        }

        CP_WAIT1();
        BAR_PAIR(jq + 1);
        if (cc + 2 < 32)
            pf_slice(slice0 + ((cc + 2) % 3) * SLICE_SZ, whsrc, efsrc, jq, cc + 2, lt);
        CP_COMMIT();

        const char*  Sc = sm + (size_t)(jq * 3 + (cc % 3)) * SLICE_SZ;
        const float* Bc = (const float*)Sc;
        const float* Ec = (const float*)(Sc + EF_OFF);

#pragma unroll
        for (int ks = 0; ks < 4; ks++) {
            float4 ef = *(const float4*)(Ec + (ks * 8 + 2 * c) * 2);
            uint32_t a0 = A0[ks].x > 0 ? tf32u(fmaxf(Ei0 * ef.x, Fi0 * ef.y)) : 0u;
            uint32_t a1 = A8[ks].x > 0 ? tf32u(fmaxf(Ei8 * ef.x, Fi8 * ef.y)) : 0u;
            uint32_t a2 = A0[ks].y > 0 ? tf32u(fmaxf(Ei0 * ef.z, Fi0 * ef.w)) : 0u;
            uint32_t a3 = A8[ks].y > 0 ? tf32u(fmaxf(Ei8 * ef.z, Fi8 * ef.w)) : 0u;
#pragma unroll
            for (int nt = 0; nt < 8; nt++) {
                float2 wv = *(const float2*)(Bc + ks * 512 + (nt * 8 + q) * 8 + 2 * c);
                MMA_TF32(acc[nt], a0, a1, a2, a3,
                         __float_as_uint(wv.x), __float_as_uint(wv.y));
            }
            MMA_TF32(acc_rs, a0, a1, a2, a3, ONE_TF, ONE_TF);
        }
#pragma unroll
        for (int ks = 0; ks < 4; ks++) { A0[ks] = nA0[ks]; A8[ks] = nA8[ks]; }
    }

    // combine the 2 j-halves via smem (reuses staging)
    float* dsm = (float*)sm;                 // [64][66]
    float* rsm = (float*)(sm + 16896);       // [64]
    __syncthreads();
    if (jq == 1) {
#pragma unroll
        for (int nt = 0; nt < 8; nt++) {
            *(float2*)(dsm + lr0 * 66 + nt * 8 + 2 * c) =
                make_float2(acc[nt][0], acc[nt][1]);
            *(float2*)(dsm + (lr0 + 8) * 66 + nt * 8 + 2 * c) =
                make_float2(acc[nt][2], acc[nt][3]);
        }
        if (c == 0) {
            rsm[lr0]     = acc_rs[0];
            rsm[lr0 + 8] = acc_rs[2];
        }
    }
    __syncthreads();
    if (jq == 0) {
        float i0v = 1.0f / (acc_rs[0] + rsm[lr0]);
        float i8v = 1.0f / (acc_rs[2] + rsm[lr0 + 8]);
        float* o0 = out + (size_t)(rowbase + i0 + lr0) * FOUT;
        float* o8 = out + (size_t)(rowbase + i0 + lr0 + 8) * FOUT;
#pragma unroll
        for (int nt = 0; nt < 8; nt++) {
            int col = nt * 8 + 2 * c;
            float2 d0 = *(const float2*)(dsm + lr0 * 66 + col);
            float2 d8 = *(const float2*)(dsm + (lr0 + 8) * 66 + col);
            float y;
            float2 v0, v8;
            y = (acc[nt][0] + d0.x) * i0v; v0.x = y > 0.f ? y : expm1f(y);
            y = (acc[nt][1] + d0.y) * i0v; v0.y = y > 0.f ? y : expm1f(y);
            y = (acc[nt][2] + d8.x) * i8v; v8.x = y > 0.f ? y : expm1f(y);
            y = (acc[nt][3] + d8.y) * i8v; v8.y = y > 0.f ? y : expm1f(y);
            *(float2*)(o0 + col) = v0;
            *(float2*)(o8 + col) = v8;
        }
    }
}

// ---------------------------------------------------------------------------
extern "C" void kernel_launch(void* const* d_in, const int* in_sizes, int n_in,
                              void* d_out, int out_size) {
    const float* h   = (const float*)d_in[0];
    const int*   adj = (const int*)d_in[1];
    const float* W   = (const float*)d_in[2];
    const float* a   = (const float*)d_in[3];
    float*       out = (float*)d_out;

    const int smemA = HB_OFF + 2 * 9216;   // 83968
    cudaFuncSetAttribute(gat_prep, cudaFuncAttributeMaxDynamicSharedMemorySize, smemA);
    cudaFuncSetAttribute(gat_attn, cudaFuncAttributeMaxDynamicSharedMemorySize, SM_TOTB);

    gat_prep<<<(B_ * N_) / 64, 256, smemA>>>(h, W, a);

    dim3 gridB(N_ / 64, B_);   // (32, 8) = 256 blocks
    gat_attn<<<gridB, 256, SM_TOTB>>>(adj, out);
}

// round 13
// speedup vs baseline: 1.1161x; 1.1161x over previous
#include <cuda_runtime.h>
#include <cstdint>

#define B_     8
#define N_     2048
#define FIN    256
#define FOUT   64
#define LOG2E  1.4426950408889634f
#define ONE_TF 0x3f800000u

// Scratch (device globals: allocation-free rule)
__device__ float    g_WhB[B_ * N_ * FOUT];  // [b][j>>3][o][j&7], tf32-pre-rounded
__device__ float    g_esrc[B_ * N_];        // log2-scaled src logits
__device__ float2   g_edEF[B_ * N_];        // per node: (exp2(d), exp2(0.2 d))

// ---------------------------------------------------------------------------
// helpers
// ---------------------------------------------------------------------------
__device__ __forceinline__ uint32_t smem_u32(const void* p) {
    uint32_t a;
    asm("{ .reg .u64 t; cvta.to.shared.u64 t, %1; cvt.u32.u64 %0, t; }" : "=r"(a) : "l"(p));
    return a;
}
__device__ __forceinline__ void cpa16(uint32_t dst, const void* src) {
    asm volatile("cp.async.cg.shared.global [%0], [%1], 16;" :: "r"(dst), "l"(src));
}
#define CP_COMMIT() asm volatile("cp.async.commit_group;" ::: "memory")
#define CP_WAIT1()  asm volatile("cp.async.wait_group 1;" ::: "memory")
#define BAR_PAIR(id) asm volatile("bar.sync %0, 128;" :: "r"(id) : "memory")

__device__ __forceinline__ float ex2f(float x) {
    float r; asm("ex2.approx.f32 %0, %1;" : "=f"(r) : "f"(x)); return r;
}
__device__ __forceinline__ uint32_t tf32u(float x) {
    uint32_t r; asm("cvt.rn.tf32.f32 %0, %1;" : "=r"(r) : "f"(x)); return r;
}
// D += A*B, m16n8k8 tf32 (base PTX ISA)
#define MMA_TF32(d, a0, a1, a2, a3, b0, b1)                                   \
    asm volatile("mma.sync.aligned.m16n8k8.row.col.f32.tf32.tf32.f32 "        \
                 "{%0,%1,%2,%3}, {%4,%5,%6,%7}, {%8,%9}, {%0,%1,%2,%3};"      \
                 : "+f"((d)[0]), "+f"((d)[1]), "+f"((d)[2]), "+f"((d)[3])     \
                 : "r"(a0), "r"(a1), "r"(a2), "r"(a3), "r"(b0), "r"(b1))

// packed fp32x2 FMA (prep kernel)
#define FMA2(d, a, b) asm("fma.rn.f32x2 %0, %1, %2, %0;" : "+l"(d) : "l"(a), "l"(b))
__device__ __forceinline__ float pair_sum(unsigned long long v) {
    float lo, hi;
    asm("mov.b64 {%0, %1}, %2;" : "=f"(lo), "=f"(hi) : "l"(v));
    return lo + hi;
}
__device__ __forceinline__ unsigned long long pack2(float lo, float hi) {
    unsigned long long r;
    asm("mov.b64 %0, {%1, %2};" : "=l"(r) : "f"(lo), "f"(hi));
    return r;
}

// ---------------------------------------------------------------------------
// Kernel PREP (round-12 version, ~20us measured): Wh = h @ W via FFMA2.
// 256 blocks x 256 threads, 64 rows/block, 2 blocks/SM (84KB smem).
// ALL of W staged pair-packed ONCE (64KB); h chunks double-buffered cp.async;
// one barrier pair per chunk. Stores g_WhB (tf32, fragment layout),
// g_esrc (log2-scaled), g_edEF = (exp2(d), exp2(0.2d)).
// ---------------------------------------------------------------------------
#define HB_OFF 65536      // byte offset of h buffers (2 x 9216)

__global__ __launch_bounds__(256, 2) void gat_prep(const float* __restrict__ h,
                                                   const float* __restrict__ W,
                                                   const float* __restrict__ a) {
    extern __shared__ char sA[];
    unsigned long long* Wp = (unsigned long long*)sA;   // 8192 ull = 64KB
    float* hb = (float*)(sA + HB_OFF);                  // 2 x (64 rows x 36)
    uint32_t hbase = smem_u32(sA) + HB_OFF;

    int t = threadIdx.x;
    int rg = t >> 4, op = t & 15;
    int row0 = blockIdx.x * 64;

    int r0 = t >> 3, f0 = t & 7;
    int r1 = (t + 256) >> 3, f1 = t & 7;
    const float* hsrc = h + (size_t)row0 * FIN;

    {   // chunks 0, 1
        cpa16(hbase + r0 * 144 + f0 * 16, hsrc + (size_t)r0 * FIN + f0 * 4);
        cpa16(hbase + r1 * 144 + f1 * 16, hsrc + (size_t)r1 * FIN + f1 * 4);
        CP_COMMIT();
        cpa16(hbase + 9216 + r0 * 144 + f0 * 16, hsrc + (size_t)r0 * FIN + 32 + f0 * 4);
        cpa16(hbase + 9216 + r1 * 144 + f1 * 16, hsrc + (size_t)r1 * FIN + 32 + f1 * 4);
        CP_COMMIT();
    }

    // stage ALL W pairs: Wp[kp*64+o] = (W[2kp][o], W[2kp+1][o]), kp 0..127
#pragma unroll 4
    for (int idx = t; idx < 8192; idx += 256) {
        int kp = idx >> 6, o = idx & 63;
        Wp[idx] = pack2(__ldg(W + (2 * kp) * FOUT + o), __ldg(W + (2 * kp + 1) * FOUT + o));
    }

    unsigned long long acc[4][4];
#pragma unroll
    for (int q = 0; q < 4; q++)
#pragma unroll
        for (int s = 0; s < 4; s++) acc[q][s] = 0ull;

    for (int c = 0; c < 8; c++) {
        CP_WAIT1();
        __syncthreads();                    // h chunk ready; also covers Wp on c==0
        const float* hc = hb + (c & 1) * 2304;
#pragma unroll
        for (int kpl = 0; kpl < 16; kpl++) {
            const ulonglong2* wrow = (const ulonglong2*)(Wp + (c * 16 + kpl) * 64);
            ulonglong2 wa = wrow[op];
            ulonglong2 wb = wrow[op + 16];
#pragma unroll
            for (int q = 0; q < 4; q++) {
                unsigned long long hv =
                    *(const unsigned long long*)(hc + (rg * 4 + q) * 36 + 2 * kpl);
                FMA2(acc[q][0], hv, wa.x);
                FMA2(acc[q][1], hv, wa.y);
                FMA2(acc[q][2], hv, wb.x);
                FMA2(acc[q][3], hv, wb.y);
            }
        }
        __syncthreads();                    // done reading hb[c&1]
        if (c + 2 < 8) {
            uint32_t dst = hbase + (c & 1) * 9216;
            const float* src = hsrc + (c + 2) * 32;
            cpa16(dst + r0 * 144 + f0 * 16, src + (size_t)r0 * FIN + f0 * 4);
            cpa16(dst + r1 * 144 + f1 * 16, src + (size_t)r1 * FIN + f1 * 4);
        }
        CP_COMMIT();
    }

    int ov[4] = {2 * op, 2 * op + 1, 2 * op + 32, 2 * op + 33};
    float a1v[4], a2v[4];
#pragma unroll
    for (int s = 0; s < 4; s++) { a1v[s] = a[ov[s]]; a2v[s] = a[FOUT + ov[s]]; }

#pragma unroll
    for (int q = 0; q < 4; q++) {
        int grow = row0 + rg * 4 + q;
        int b = grow >> 11, n = grow & (N_ - 1);
        float vals[4], v1 = 0.f, v2 = 0.f;
#pragma unroll
        for (int s = 0; s < 4; s++) {
            vals[s] = pair_sum(acc[q][s]);
            v1 += vals[s] * a1v[s];
            v2 += vals[s] * a2v[s];
        }
        size_t base = ((size_t)b * 256 + (n >> 3)) * 512 + (n & 7);
#pragma unroll
        for (int s = 0; s < 4; s++)
            g_WhB[base + (size_t)ov[s] * 8] = __uint_as_float(tf32u(vals[s]));
#pragma unroll
        for (int off = 1; off < 16; off <<= 1) {
            v1 += __shfl_xor_sync(0xffffffffu, v1, off);
            v2 += __shfl_xor_sync(0xffffffffu, v2, off);
        }
        if (op == 0) {
            float s = v1 * LOG2E, d = v2 * LOG2E;
            g_esrc[grow] = s;
            g_edEF[grow] = make_float2(ex2f(d), ex2f(0.2f * d));
        }
    }
}

// ---------------------------------------------------------------------------
// Kernel B (round-11 version, 44.9us measured): raw-adj smem-staged
// streaming attention -> mma.sync tf32 P @ Wh.
// Grid (32,8)=256 blocks x 256 threads, 2 blocks/SM.
// 2 PAIRS of 4 warps: jq = w>>2 (j-half), wp = w&3 (one m16 fragment).
// Slice = Wh tile (8KB) + RAW adj tile 64x32 int (stride 36, 9KB) + EF,
// triple-buffered cp.async (fully coalesced), pair-scoped named barrier.
// adj touched exactly once chip-wide.
// p = adj>0 ? max(Ei*Ej, Fi*Fj) : 0 (== exp2(leaky)), tf32.
// Rowsum via ones-B MMA (same tf32 p -> exact normalization).
// ---------------------------------------------------------------------------
#define ADJ_OFF  8192
#define EF_OFF   17408
#define SLICE_SZ 17664                     // 8192 Wh + 9216 adj + 256 EF
#define SM_TOTB  (2 * 3 * SLICE_SZ)        // 105984

__device__ __forceinline__ void pf_slice(uint32_t dst, const char* whsrc,
                                         const char* adjsrc, const float2* efsrc,
                                         int jq, int cc, int lt) {
    const char* wsrc = whsrc + (size_t)(jq * 128 + cc * 4) * 2048;
#pragma unroll
    for (int i = 0; i < 4; i++)
        cpa16(dst + (lt + 128 * i) * 16, wsrc + (size_t)(lt + 128 * i) * 16);
#pragma unroll
    for (int i = 0; i < 4; i++) {
        int idx = i * 128 + lt;            // 512 x 16B
        int r = idx >> 3, u = idx & 7;
        cpa16(dst + ADJ_OFF + r * 144 + u * 16,
              adjsrc + ((size_t)r << 13) + (size_t)(jq * 4096 + cc * 128) + u * 16);
    }
    if (lt < 16)
        cpa16(dst + EF_OFF + lt * 16,
              (const char*)(efsrc + (size_t)jq * 1024 + cc * 32) + lt * 16);
}

__global__ __launch_bounds__(256, 2) void gat_attn(const int* __restrict__ adj,
                                                   float* __restrict__ out) {
    extern __shared__ char sm[];
    uint32_t smb = smem_u32(sm);

    int t = threadIdx.x;
    int w = t >> 5, lane = t & 31;
    int q = lane >> 2, c = lane & 3;
    int b = blockIdx.y;
    int i0 = blockIdx.x * 64;
    int rowbase = b * N_;
    int jq = w >> 2, wp = w & 3;
    int lr0 = wp * 16 + q;
    int lt = t & 127;
    uint32_t slice0 = smb + jq * 3 * SLICE_SZ;

    const char*   whsrc  = (const char*)(g_WhB + (size_t)b * N_ * FOUT);
    const char*   adjsrc = (const char*)(adj + ((size_t)(rowbase + i0) << 11));
    const float2* efsrc  = g_edEF + rowbase;

    float si0 = g_esrc[rowbase + i0 + lr0];
    float si8 = g_esrc[rowbase + i0 + lr0 + 8];
    float Ei0 = ex2f(si0), Fi0 = ex2f(0.2f * si0);
    float Ei8 = ex2f(si8), Fi8 = ex2f(0.2f * si8);

    pf_slice(slice0, whsrc, adjsrc, efsrc, jq, 0, lt);            CP_COMMIT();
    pf_slice(slice0 + SLICE_SZ, whsrc, adjsrc, efsrc, jq, 1, lt); CP_COMMIT();

    float acc[8][4];
#pragma unroll
    for (int nt = 0; nt < 8; nt++)
#pragma unroll
        for (int s = 0; s < 4; s++) acc[nt][s] = 0.f;
    float acc_rs[4] = {0.f, 0.f, 0.f, 0.f};

#pragma unroll 1
    for (int cc = 0; cc < 32; cc++) {
        CP_WAIT1();
        BAR_PAIR(jq + 1);
        if (cc + 2 < 32)
            pf_slice(slice0 + ((cc + 2) % 3) * SLICE_SZ, whsrc, adjsrc, efsrc,
                     jq, cc + 2, lt);
        CP_COMMIT();

        const char*  Sc = sm + (size_t)(jq * 3 + (cc % 3)) * SLICE_SZ;
        const float* Bc = (const float*)Sc;
        const int*   Ac = (const int*)(Sc + ADJ_OFF);
        const float* Ec = (const float*)(Sc + EF_OFF);

        int2 A0[4], A8[4];
#pragma unroll
        for (int ks = 0; ks < 4; ks++) {
            A0[ks] = *(const int2*)(Ac + lr0 * 36 + ks * 8 + 2 * c);
            A8[ks] = *(const int2*)(Ac + (lr0 + 8) * 36 + ks * 8 + 2 * c);
        }

#pragma unroll
        for (int ks = 0; ks < 4; ks++) {
            float4 ef = *(const float4*)(Ec + (ks * 8 + 2 * c) * 2);
            uint32_t a0 = A0[ks].x > 0 ? tf32u(fmaxf(Ei0 * ef.x, Fi0 * ef.y)) : 0u;
            uint32_t a1 = A8[ks].x > 0 ? tf32u(fmaxf(Ei8 * ef.x, Fi8 * ef.y)) : 0u;
            uint32_t a2 = A0[ks].y > 0 ? tf32u(fmaxf(Ei0 * ef.z, Fi0 * ef.w)) : 0u;
            uint32_t a3 = A8[ks].y > 0 ? tf32u(fmaxf(Ei8 * ef.z, Fi8 * ef.w)) : 0u;
#pragma unroll
            for (int nt = 0; nt < 8; nt++) {
                float2 wv = *(const float2*)(Bc + ks * 512 + (nt * 8 + q) * 8 + 2 * c);
                MMA_TF32(acc[nt], a0, a1, a2, a3,
                         __float_as_uint(wv.x), __float_as_uint(wv.y));
            }
            MMA_TF32(acc_rs, a0, a1, a2, a3, ONE_TF, ONE_TF);
        }
    }

    // combine the 2 j-halves via smem (reuses staging)
    float* dsm = (float*)sm;                 // [64][66]
    float* rsm = (float*)(sm + 16896);       // [64]
    __syncthreads();
    if (jq == 1) {
#pragma unroll
        for (int nt = 0; nt < 8; nt++) {
            *(float2*)(dsm + lr0 * 66 + nt * 8 + 2 * c) =
                make_float2(acc[nt][0], acc[nt][1]);
            *(float2*)(dsm + (lr0 + 8) * 66 + nt * 8 + 2 * c) =
                make_float2(acc[nt][2], acc[nt][3]);
        }
        if (c == 0) {
            rsm[lr0]     = acc_rs[0];
            rsm[lr0 + 8] = acc_rs[2];
        }
    }
    __syncthreads();
    if (jq == 0) {
        float i0v = 1.0f / (acc_rs[0] + rsm[lr0]);
        float i8v = 1.0f / (acc_rs[2] + rsm[lr0 + 8]);
        float* o0 = out + (size_t)(rowbase + i0 + lr0) * FOUT;
        float* o8 = out + (size_t)(rowbase + i0 + lr0 + 8) * FOUT;
#pragma unroll
        for (int nt = 0; nt < 8; nt++) {
            int col = nt * 8 + 2 * c;
            float2 d0 = *(const float2*)(dsm + lr0 * 66 + col);
            float2 d8 = *(const float2*)(dsm + (lr0 + 8) * 66 + col);
            float y;
            float2 v0, v8;
            y = (acc[nt][0] + d0.x) * i0v; v0.x = y > 0.f ? y : expm1f(y);
            y = (acc[nt][1] + d0.y) * i0v; v0.y = y > 0.f ? y : expm1f(y);
            y = (acc[nt][2] + d8.x) * i8v; v8.x = y > 0.f ? y : expm1f(y);
            y = (acc[nt][3] + d8.y) * i8v; v8.y = y > 0.f ? y : expm1f(y);
            *(float2*)(o0 + col) = v0;
            *(float2*)(o8 + col) = v8;
        }
    }
}

// ---------------------------------------------------------------------------
extern "C" void kernel_launch(void* const* d_in, const int* in_sizes, int n_in,
                              void* d_out, int out_size) {
    const float* h   = (const float*)d_in[0];
    const int*   adj = (const int*)d_in[1];
    const float* W   = (const float*)d_in[2];
    const float* a   = (const float*)d_in[3];
    float*       out = (float*)d_out;

    const int smemA = HB_OFF + 2 * 9216;   // 83968
    cudaFuncSetAttribute(gat_prep, cudaFuncAttributeMaxDynamicSharedMemorySize, smemA);
    cudaFuncSetAttribute(gat_attn, cudaFuncAttributeMaxDynamicSharedMemorySize, SM_TOTB);

    gat_prep<<<(B_ * N_) / 64, 256, smemA>>>(h, W, a);

    dim3 gridB(N_ / 64, B_);   // (32, 8) = 256 blocks
    gat_attn<<<gridB, 256, SM_TOTB>>>(adj, out);
}